// round 15
// baseline (speedup 1.0000x reference)
#include <cuda_runtime.h>
#include <cuda_bf16.h>
#include <cstdint>

// LSTM: B=32, T=1024, I=512, H=512, gates G=4H=2048
// out layout: outs[B][T][H] (16777216 floats) | h_T[B][H] | c_T[B][H]

#define NB 32
#define NT 1024
#define NI 512
#define NH 512
#define NG 2048

#define GROUPS 4
#define GBLK 32
#define GBATCH 8
#define SCAN_BLOCKS (GROUPS * GBLK)
#define SCAN_THREADS 512

// ---------------- device scratch ----------------
__device__ float g_xg[(size_t)NT * NB * NG];      // [t][b][g]
__device__ unsigned g_flags[GROUPS * 32];         // per-block step flags (1 line per group)
__device__ __nv_bfloat16 g_xh[(size_t)NB * NT * NI];   // x hi split
__device__ __nv_bfloat16 g_xl[(size_t)NB * NT * NI];   // x lo split
__device__ __nv_bfloat16 g_wh[(size_t)NG * NI];        // W_ih hi split
__device__ __nv_bfloat16 g_wl[(size_t)NG * NI];        // W_ih lo split
// hidden state as bf16 hi/lo, [b][j] contiguous j, double-buffered
__device__ unsigned short g_hh[2][NB * NH];
__device__ unsigned short g_hl[2][NB * NH];

__device__ __forceinline__ float sigf(float x) {
    return 1.0f / (1.0f + __expf(-x));
}
__device__ __forceinline__ float tanhfast(float x) {
    return 1.0f - 2.0f / (__expf(2.0f * x) + 1.0f);
}
__device__ __forceinline__ uint32_t smem_u32(const void* p) {
    uint32_t a;
    asm("{ .reg .u64 t; cvta.to.shared.u64 t, %1; cvt.u32.u64 %0, t; }" : "=r"(a) : "l"(p));
    return a;
}
__device__ __forceinline__ uint32_t swz(uint32_t off) { return off ^ ((off >> 3) & 0x70); }

#define CP_ASYNC16(dst, src) \
    asm volatile("cp.async.cg.shared.global [%0], [%1], 16;" :: "r"(dst), "l"(src))
#define CP_COMMIT() asm volatile("cp.async.commit_group;" ::: "memory")

#define LDSM_X4(r0, r1, r2, r3, a) \
    asm volatile("ldmatrix.sync.aligned.m8n8.x4.shared.b16 {%0,%1,%2,%3}, [%4];" \
                 : "=r"(r0), "=r"(r1), "=r"(r2), "=r"(r3) : "r"(a))

#define MMA16816(c, a, b0, b1) \
    asm volatile("mma.sync.aligned.m16n8k16.row.col.f32.bf16.bf16.f32 " \
                 "{%0,%1,%2,%3}, {%4,%5,%6,%7}, {%8,%9}, {%0,%1,%2,%3};" \
                 : "+f"((c)[0]), "+f"((c)[1]), "+f"((c)[2]), "+f"((c)[3]) \
                 : "r"((a)[0]), "r"((a)[1]), "r"((a)[2]), "r"((a)[3]), \
                   "r"(b0), "r"(b1))

// pack two floats into hi-bf16x2 (ret) and lo-bf16x2 (out param)
__device__ __forceinline__ uint32_t pack_hilo2(float a, float b, uint32_t& lo) {
    __nv_bfloat16 ha = __float2bfloat16_rn(a);
    __nv_bfloat16 hb = __float2bfloat16_rn(b);
    __nv_bfloat16 la = __float2bfloat16_rn(a - __bfloat162float(ha));
    __nv_bfloat16 lb = __float2bfloat16_rn(b - __bfloat162float(hb));
    lo = (uint32_t)__bfloat16_as_ushort(la) | ((uint32_t)__bfloat16_as_ushort(lb) << 16);
    return (uint32_t)__bfloat16_as_ushort(ha) | ((uint32_t)__bfloat16_as_ushort(hb) << 16);
}

// ---------------- split + init kernel (runs every replay) ----------------
__global__ void __launch_bounds__(256) k_split(const float* __restrict__ X,
                                               const float* __restrict__ Wih) {
    const int gtid = threadIdx.x + blockIdx.x * blockDim.x;
    const int nthr = gridDim.x * blockDim.x;

    for (int i = gtid; i < GROUPS * 32; i += nthr) g_flags[i] = 0u;
    for (int i = gtid; i < NB * NH / 8; i += nthr) {
        ((uint4*)&g_hh[0][0])[i] = make_uint4(0, 0, 0, 0);
        ((uint4*)&g_hl[0][0])[i] = make_uint4(0, 0, 0, 0);
    }

    for (int i = gtid; i < NB * NT * NI / 4; i += nthr) {
        float4 v = __ldg((const float4*)X + i);
        const float* f = (const float*)&v;
        unsigned hi[2] = {0, 0}, lo[2] = {0, 0};
#pragma unroll
        for (int j = 0; j < 4; j++) {
            __nv_bfloat16 h = __float2bfloat16_rn(f[j]);
            __nv_bfloat16 l = __float2bfloat16_rn(f[j] - __bfloat162float(h));
            hi[j >> 1] |= (unsigned)__bfloat16_as_ushort(h) << ((j & 1) * 16);
            lo[j >> 1] |= (unsigned)__bfloat16_as_ushort(l) << ((j & 1) * 16);
        }
        ((uint2*)g_xh)[i] = make_uint2(hi[0], hi[1]);
        ((uint2*)g_xl)[i] = make_uint2(lo[0], lo[1]);
    }
    for (int i = gtid; i < NG * NI / 4; i += nthr) {
        float4 v = __ldg((const float4*)Wih + i);
        const float* f = (const float*)&v;
        unsigned hi[2] = {0, 0}, lo[2] = {0, 0};
#pragma unroll
        for (int j = 0; j < 4; j++) {
            __nv_bfloat16 h = __float2bfloat16_rn(f[j]);
            __nv_bfloat16 l = __float2bfloat16_rn(f[j] - __bfloat162float(h));
            hi[j >> 1] |= (unsigned)__bfloat16_as_ushort(h) << ((j & 1) * 16);
            lo[j >> 1] |= (unsigned)__bfloat16_as_ushort(l) << ((j & 1) * 16);
        }
        ((uint2*)g_wh)[i] = make_uint2(hi[0], hi[1]);
        ((uint2*)g_wl)[i] = make_uint2(lo[0], lo[1]);
    }
}

// ---------------- mma.sync GEMM (unchanged — passing) ----------------
#define GHDR 1024
#define PANEL 16384
#define GBUF (4 * PANEL)

__device__ __forceinline__ void gemm_load_stage(uint32_t sb, uint32_t bufb, int kb,
                                                int tid, int m0, int n0) {
#pragma unroll
    for (int i = 0; i < 16; i++) {
        const int idx = tid + i * 256;
        const int panel = idx >> 10;
        const int row = (idx >> 3) & 127;
        const int sg = idx & 7;
        const __nv_bfloat16* src;
        if (panel == 0)      src = g_xh + (size_t)(m0 + row) * NI + kb + 8 * sg;
        else if (panel == 1) src = g_xl + (size_t)(m0 + row) * NI + kb + 8 * sg;
        else if (panel == 2) src = g_wh + (size_t)(n0 + row) * NI + kb + 8 * sg;
        else                 src = g_wl + (size_t)(n0 + row) * NI + kb + 8 * sg;
        CP_ASYNC16(sb + bufb + panel * PANEL + swz(row * 128 + sg * 16), src);
    }
}

__global__ void __launch_bounds__(256) k_gemm_mma(const float* __restrict__ bih,
                                                  const float* __restrict__ bhh) {
    extern __shared__ char smem[];
    const uint32_t sb = smem_u32(smem);
    const int tid = threadIdx.x;
    const int wid = tid >> 5;
    const int lane = tid & 31;
    const int n0 = blockIdx.x * 128;
    const int m0 = blockIdx.y * 128;
    float* sBias = (float*)smem;

    const int wm = wid & 1;
    const int wn = wid >> 1;

    if (tid < 128) sBias[tid] = __ldg(bih + n0 + tid) + __ldg(bhh + n0 + tid);

    uint32_t baseA[4], xorA[4];
#pragma unroll
    for (int mt = 0; mt < 4; mt++) {
        const int rA = wm * 64 + mt * 16 + (lane & 15);
        baseA[mt] = (uint32_t)rA * 128;
        xorA[mt] = (uint32_t)(rA & 7) << 4;
    }
    const uint32_t cA0 = (uint32_t)(lane >> 4) * 16;
    const int gB = lane >> 3;
    uint32_t baseB[2], xorB[2];
#pragma unroll
    for (int pr = 0; pr < 2; pr++) {
        const int rB = wn * 32 + pr * 16 + ((gB >> 1) << 3) + (lane & 7);
        baseB[pr] = (uint32_t)rB * 128;
        xorB[pr] = (uint32_t)(rB & 7) << 4;
    }
    const uint32_t cB0 = (uint32_t)(gB & 1) * 16;

    float acc[4][4][4];
#pragma unroll
    for (int mt = 0; mt < 4; mt++)
#pragma unroll
        for (int nt = 0; nt < 4; nt++)
#pragma unroll
            for (int e = 0; e < 4; e++) acc[mt][nt][e] = 0.0f;

    gemm_load_stage(sb, GHDR, 0, tid, m0, n0);
    CP_COMMIT();

    for (int s = 0; s < 8; s++) {
        const uint32_t bufb = GHDR + (uint32_t)(s & 1) * GBUF;
        if (s < 7) {
            gemm_load_stage(sb, GHDR + (uint32_t)((s + 1) & 1) * GBUF, (s + 1) * 64, tid, m0, n0);
            CP_COMMIT();
            asm volatile("cp.async.wait_group 1;" ::: "memory");
        } else {
            asm volatile("cp.async.wait_group 0;" ::: "memory");
        }
        __syncthreads();

        const uint32_t pAh = sb + bufb + 0 * PANEL;
        const uint32_t pAl = sb + bufb + 1 * PANEL;
        const uint32_t pBh = sb + bufb + 2 * PANEL;
        const uint32_t pBl = sb + bufb + 3 * PANEL;

#pragma unroll
        for (int k16 = 0; k16 < 4; k16++) {
            const uint32_t cA = (uint32_t)k16 * 32 + cA0;
            const uint32_t cB = (uint32_t)k16 * 32 + cB0;

            uint32_t ah[4][4], al[4][4], bh[2][4], bl[2][4];
#pragma unroll
            for (int mt = 0; mt < 4; mt++) {
                LDSM_X4(ah[mt][0], ah[mt][1], ah[mt][2], ah[mt][3],
                        pAh + baseA[mt] + (cA ^ xorA[mt]));
                LDSM_X4(al[mt][0], al[mt][1], al[mt][2], al[mt][3],
                        pAl + baseA[mt] + (cA ^ xorA[mt]));
            }
#pragma unroll
            for (int pr = 0; pr < 2; pr++) {
                LDSM_X4(bh[pr][0], bh[pr][1], bh[pr][2], bh[pr][3],
                        pBh + baseB[pr] + (cB ^ xorB[pr]));
                LDSM_X4(bl[pr][0], bl[pr][1], bl[pr][2], bl[pr][3],
                        pBl + baseB[pr] + (cB ^ xorB[pr]));
            }
#pragma unroll
            for (int mt = 0; mt < 4; mt++)
#pragma unroll
                for (int nt = 0; nt < 4; nt++) {
                    const int pr = nt >> 1;
                    const int sub = nt & 1;
                    MMA16816(acc[mt][nt], ah[mt], bh[pr][sub * 2], bh[pr][sub * 2 + 1]);
                    MMA16816(acc[mt][nt], al[mt], bh[pr][sub * 2], bh[pr][sub * 2 + 1]);
                    MMA16816(acc[mt][nt], ah[mt], bl[pr][sub * 2], bl[pr][sub * 2 + 1]);
                }
        }
        __syncthreads();
    }

    const int b = m0 >> 10;
#pragma unroll
    for (int mt = 0; mt < 4; mt++) {
        const int mrow0 = m0 + wm * 64 + mt * 16 + (lane >> 2);
        const int t0 = mrow0 & (NT - 1);
        const int t1 = (mrow0 + 8) & (NT - 1);
        float* d0 = g_xg + ((size_t)t0 * NB + b) * NG + n0;
        float* d1 = g_xg + ((size_t)t1 * NB + b) * NG + n0;
#pragma unroll
        for (int nt = 0; nt < 4; nt++) {
            const int bn = wn * 32 + nt * 8 + 2 * (lane & 3);
            const float bz0 = sBias[bn], bz1 = sBias[bn + 1];
            *(float2*)(d0 + bn) = make_float2(acc[mt][nt][0] + bz0, acc[mt][nt][1] + bz1);
            *(float2*)(d1 + bn) = make_float2(acc[mt][nt][2] + bz0, acc[mt][nt][3] + bz1);
        }
    }
}

// ---------------- persistent tensor-core scan (v7: flag-array barrier) ----------------
// Structure as v6 (4 groups x 32 blocks, W frags in regs, spread finalize).
// v7 change: the group barrier is a 32-word flag line per group —
// arrive = st.release.gpu flags[rank] = t+1 (no RMW serialization);
// discover = warp 0 lanes poll all 32 flags with ld.acquire (one coalesced
// 128B L2 read per iteration) + __any_sync.
#define HROW 1040
#define SOFF_HI 0
#define SOFF_LO (GBATCH * HROW)              // 8320
#define SOFF_RED (2 * GBATCH * HROW)         // 16640
#define SOFF_FIN (SOFF_RED + 8 * 512 * 4)    // 33024
#define SCAN_SMEM (SOFF_FIN + 512 * 4)       // 35072

__global__ void __launch_bounds__(SCAN_THREADS, 1) k_scan(float* __restrict__ out,
                                                          const float* __restrict__ Whh) {
    extern __shared__ char sm[];
    const uint32_t sb = smem_u32(sm);
    float* sRed = (float*)(sm + SOFF_RED);
    float* sFin = (float*)(sm + SOFF_FIN);

    const int tid = threadIdx.x;
    const int bid = blockIdx.x;
    const int gid = bid >> 5;
    const int rank = bid & 31;
    const int j0 = rank * 16;
    const int wid = tid >> 5;
    const int lane = tid & 31;
    const int kc = wid >> 1;          // k in [64kc, 64kc+64)
    const int mh = wid & 1;           // rows mh*32 .. +31

    // ---- build W_hh fragments directly from global fp32 (A-frag lane map) ----
    uint32_t ah[2][4][4], al[2][4][4];
#pragma unroll
    for (int mt = 0; mt < 2; mt++) {
        const int mlo = mh * 32 + mt * 16 + (lane >> 2);
        const int mhi2 = mlo + 8;
        const size_t row0 = (size_t)((mlo >> 4) * 512 + j0 + (mlo & 15)) * NH;
        const size_t row1 = (size_t)((mhi2 >> 4) * 512 + j0 + (mhi2 & 15)) * NH;
#pragma unroll
        for (int ks = 0; ks < 4; ks++) {
            const int kb = kc * 64 + ks * 16 + 2 * (lane & 3);
            float2 v00 = *(const float2*)(Whh + row0 + kb);
            float2 v10 = *(const float2*)(Whh + row1 + kb);
            float2 v01 = *(const float2*)(Whh + row0 + kb + 8);
            float2 v11 = *(const float2*)(Whh + row1 + kb + 8);
            ah[mt][ks][0] = pack_hilo2(v00.x, v00.y, al[mt][ks][0]);
            ah[mt][ks][1] = pack_hilo2(v10.x, v10.y, al[mt][ks][1]);
            ah[mt][ks][2] = pack_hilo2(v01.x, v01.y, al[mt][ks][2]);
            ah[mt][ks][3] = pack_hilo2(v11.x, v11.y, al[mt][ks][3]);
        }
    }

    // B ldmatrix per-lane base: row = lane&7 (batch), k-byte = (lane>>3)*16
    const uint32_t bOff = (uint32_t)(lane & 7) * HROW + (uint32_t)(lane >> 3) * 16;

    // gate-phase roles (ALL 512 threads): q = tid>>7, pair = tid&127
    const int gq = tid >> 7;
    const int gpair = tid & 127;               // fu*8 + fb
    const int gfb = gpair & 7;
    const int gfu = gpair >> 3;
    const int ggb = gid * GBATCH + gfb;        // global batch for gate thread

    // cell-phase roles (tid < 128): pair = tid
    const int cfb = tid & 7;
    const int cfu = tid >> 3;
    const int cgb = gid * GBATCH + cfb;

    float creg = 0.0f;

    // per-thread xg prefetch (one value: gate gq of unit gfu, batch ggb)
    float xgv = __ldcg(g_xg + ((size_t)ggb) * NG + gq * 512 + j0 + gfu);

    const int m0r = lane >> 2;
    const int bc0 = 2 * (lane & 3);

    unsigned* const flagp = &g_flags[gid * 32];

    for (int t = 0; t < NT; t++) {
        const int cur = t & 1;
        const int nxt = cur ^ 1;

        // ---- stage group's h hi/lo (8KB each) ----
        {
            const uint4* srcH = (const uint4*)&g_hh[cur][gid * GBATCH * NH];
            const uint4* srcL = (const uint4*)&g_hl[cur][gid * GBATCH * NH];
            const int b = tid >> 6;
            const int kch = tid & 63;
            uint4 vh = __ldcg(srcH + tid);
            uint4 vl = __ldcg(srcL + tid);
            *(uint4*)(sm + SOFF_HI + b * HROW + kch * 16) = vh;
            *(uint4*)(sm + SOFF_LO + b * HROW + kch * 16) = vl;
        }
        __syncthreads();

        // ---- tensor dot: 4 LDSM.x4 + 24 mma ----
        float acc[2][4];
#pragma unroll
        for (int mt = 0; mt < 2; mt++)
#pragma unroll
            for (int e = 0; e < 4; e++) acc[mt][e] = 0.0f;

#pragma unroll
        for (int kh = 0; kh < 2; kh++) {
            const uint32_t cofs = (uint32_t)(kc * 64 + kh * 32) * 2;
            uint32_t bh[4], bl[4];
            LDSM_X4(bh[0], bh[1], bh[2], bh[3], sb + SOFF_HI + bOff + cofs);
            LDSM_X4(bl[0], bl[1], bl[2], bl[3], sb + SOFF_LO + bOff + cofs);
#pragma unroll
            for (int ki = 0; ki < 2; ki++) {
                const int ks = kh * 2 + ki;
#pragma unroll
                for (int mt = 0; mt < 2; mt++) {
                    MMA16816(acc[mt], ah[mt][ks], bh[ki * 2], bh[ki * 2 + 1]);
                    MMA16816(acc[mt], al[mt][ks], bh[ki * 2], bh[ki * 2 + 1]);
                    MMA16816(acc[mt], ah[mt][ks], bl[ki * 2], bl[ki * 2 + 1]);
                }
            }
        }

        // ---- store partials: col = m*8 + b = q*128 + pair ----
#pragma unroll
        for (int mt = 0; mt < 2; mt++) {
            const int mA = mh * 32 + mt * 16 + m0r;
            *(float2*)&sRed[kc * 512 + mA * 8 + bc0] = make_float2(acc[mt][0], acc[mt][1]);
            *(float2*)&sRed[kc * 512 + (mA + 8) * 8 + bc0] = make_float2(acc[mt][2], acc[mt][3]);
        }
        __syncthreads();

        // ---- gate phase: 512 threads, one gate value each ----
        {
            float s = xgv;
            const int col = gq * 128 + gpair;
#pragma unroll
            for (int r = 0; r < 8; r++) s += sRed[r * 512 + col];
            if (t + 1 < NT)
                xgv = __ldcg(g_xg + ((size_t)(t + 1) * NB + ggb) * NG + gq * 512 + j0 + gfu);
            const float act = (gq == 2) ? tanhfast(s) : sigf(s);
            sFin[gq * 128 + gpair] = act;
        }
        __syncthreads();

        // ---- cell phase: 128 threads ----
        if (tid < 128) {
            const float ig = sFin[tid];
            const float fg = sFin[128 + tid];
            const float gv = sFin[256 + tid];
            const float og = sFin[384 + tid];
            creg = fg * creg + ig * gv;
            const float hn = og * tanhfast(creg);

            const int j = j0 + cfu;
            out[((size_t)cgb * NT + t) * NH + j] = hn;

            const __nv_bfloat16 hh = __float2bfloat16_rn(hn);
            const __nv_bfloat16 hl = __float2bfloat16_rn(hn - __bfloat162float(hh));
            g_hh[nxt][cgb * NH + j] = __bfloat16_as_ushort(hh);
            g_hl[nxt][cgb * NH + j] = __bfloat16_as_ushort(hl);

            if (t == NT - 1) {
                out[(size_t)NB * NT * NH + (size_t)cgb * NH + j] = hn;
                out[(size_t)NB * NT * NH + (size_t)NB * NH + (size_t)cgb * NH + j] = creg;
            }
        }
        __syncthreads();

        // ---- group barrier: per-rank flag store + warp-parallel coalesced poll ----
        if (tid == 0)
            asm volatile("st.release.gpu.u32 [%0], %1;"
                         :: "l"(flagp + rank), "r"((unsigned)(t + 1)) : "memory");
        if (wid == 0) {
            const unsigned tgt = (unsigned)(t + 1);
            unsigned v;
            do {
                asm volatile("ld.acquire.gpu.u32 %0, [%1];"
                             : "=r"(v) : "l"(flagp + lane) : "memory");
            } while (__any_sync(0xffffffffu, v < tgt));
        }
        __syncthreads();
    }
}

// ---------------- launch ----------------
extern "C" void kernel_launch(void* const* d_in, const int* in_sizes, int n_in,
                              void* d_out, int out_size) {
    const float* x    = (const float*)d_in[0];
    const float* Wih  = (const float*)d_in[1];
    const float* Whh  = (const float*)d_in[2];
    const float* bih  = (const float*)d_in[3];
    const float* bhh  = (const float*)d_in[4];
    float* out = (float*)d_out;

    const int gemm_smem = GHDR + 2 * GBUF;   // 132,096 B
    cudaFuncSetAttribute(k_gemm_mma, cudaFuncAttributeMaxDynamicSharedMemorySize, gemm_smem);
    cudaFuncSetAttribute(k_scan, cudaFuncAttributeMaxDynamicSharedMemorySize, SCAN_SMEM);

    k_split<<<1024, 256>>>(x, Wih);

    dim3 ggrid(NG / 128, (NB * NT) / 128);   // (16, 256)
    k_gemm_mma<<<ggrid, 256, gemm_smem>>>(bih, bhh);

    k_scan<<<SCAN_BLOCKS, SCAN_THREADS, SCAN_SMEM>>>(out, Whh);
}

// round 17
// speedup vs baseline: 2.7700x; 2.7700x over previous
#include <cuda_runtime.h>
#include <cuda_bf16.h>
#include <cstdint>

// LSTM: B=32, T=1024, I=512, H=512, gates G=4H=2048
// out layout: outs[B][T][H] (16777216 floats) | h_T[B][H] | c_T[B][H]

#define NB 32
#define NT 1024
#define NI 512
#define NH 512
#define NG 2048

#define GROUPS 4
#define GBLK 32
#define GBATCH 8
#define SCAN_BLOCKS (GROUPS * GBLK)
#define SCAN_THREADS 512

// ---------------- device scratch ----------------
__device__ float g_xg[(size_t)NT * NB * NG];      // [t][b][g]
__device__ unsigned g_bars[GROUPS * 32];          // per-group monotonic counters (padded)
__device__ __nv_bfloat16 g_xh[(size_t)NB * NT * NI];   // x hi split
__device__ __nv_bfloat16 g_xl[(size_t)NB * NT * NI];   // x lo split
__device__ __nv_bfloat16 g_wh[(size_t)NG * NI];        // W_ih hi split
__device__ __nv_bfloat16 g_wl[(size_t)NG * NI];        // W_ih lo split
// hidden state as bf16 hi/lo, [b][j] contiguous j, double-buffered
__device__ unsigned short g_hh[2][NB * NH];
__device__ unsigned short g_hl[2][NB * NH];

__device__ __forceinline__ float sigf(float x) {
    return 1.0f / (1.0f + __expf(-x));
}
__device__ __forceinline__ float tanhfast(float x) {
    return 1.0f - 2.0f / (__expf(2.0f * x) + 1.0f);
}
__device__ __forceinline__ uint32_t smem_u32(const void* p) {
    uint32_t a;
    asm("{ .reg .u64 t; cvta.to.shared.u64 t, %1; cvt.u32.u64 %0, t; }" : "=r"(a) : "l"(p));
    return a;
}
__device__ __forceinline__ uint32_t swz(uint32_t off) { return off ^ ((off >> 3) & 0x70); }

#define CP_ASYNC16(dst, src) \
    asm volatile("cp.async.cg.shared.global [%0], [%1], 16;" :: "r"(dst), "l"(src))
#define CP_COMMIT() asm volatile("cp.async.commit_group;" ::: "memory")

#define LDSM_X4(r0, r1, r2, r3, a) \
    asm volatile("ldmatrix.sync.aligned.m8n8.x4.shared.b16 {%0,%1,%2,%3}, [%4];" \
                 : "=r"(r0), "=r"(r1), "=r"(r2), "=r"(r3) : "r"(a))

#define MMA16816(c, a, b0, b1) \
    asm volatile("mma.sync.aligned.m16n8k16.row.col.f32.bf16.bf16.f32 " \
                 "{%0,%1,%2,%3}, {%4,%5,%6,%7}, {%8,%9}, {%0,%1,%2,%3};" \
                 : "+f"((c)[0]), "+f"((c)[1]), "+f"((c)[2]), "+f"((c)[3]) \
                 : "r"((a)[0]), "r"((a)[1]), "r"((a)[2]), "r"((a)[3]), \
                   "r"(b0), "r"(b1))

// pack two floats into hi-bf16x2 (ret) and lo-bf16x2 (out param)
__device__ __forceinline__ uint32_t pack_hilo2(float a, float b, uint32_t& lo) {
    __nv_bfloat16 ha = __float2bfloat16_rn(a);
    __nv_bfloat16 hb = __float2bfloat16_rn(b);
    __nv_bfloat16 la = __float2bfloat16_rn(a - __bfloat162float(ha));
    __nv_bfloat16 lb = __float2bfloat16_rn(b - __bfloat162float(hb));
    lo = (uint32_t)__bfloat16_as_ushort(la) | ((uint32_t)__bfloat16_as_ushort(lb) << 16);
    return (uint32_t)__bfloat16_as_ushort(ha) | ((uint32_t)__bfloat16_as_ushort(hb) << 16);
}

// ---------------- split + init kernel (runs every replay) ----------------
__global__ void __launch_bounds__(256) k_split(const float* __restrict__ X,
                                               const float* __restrict__ Wih) {
    const int gtid = threadIdx.x + blockIdx.x * blockDim.x;
    const int nthr = gridDim.x * blockDim.x;

    for (int i = gtid; i < GROUPS * 32; i += nthr) g_bars[i] = 0u;
    for (int i = gtid; i < NB * NH / 8; i += nthr) {
        ((uint4*)&g_hh[0][0])[i] = make_uint4(0, 0, 0, 0);
        ((uint4*)&g_hl[0][0])[i] = make_uint4(0, 0, 0, 0);
    }

    for (int i = gtid; i < NB * NT * NI / 4; i += nthr) {
        float4 v = __ldg((const float4*)X + i);
        const float* f = (const float*)&v;
        unsigned hi[2] = {0, 0}, lo[2] = {0, 0};
#pragma unroll
        for (int j = 0; j < 4; j++) {
            __nv_bfloat16 h = __float2bfloat16_rn(f[j]);
            __nv_bfloat16 l = __float2bfloat16_rn(f[j] - __bfloat162float(h));
            hi[j >> 1] |= (unsigned)__bfloat16_as_ushort(h) << ((j & 1) * 16);
            lo[j >> 1] |= (unsigned)__bfloat16_as_ushort(l) << ((j & 1) * 16);
        }
        ((uint2*)g_xh)[i] = make_uint2(hi[0], hi[1]);
        ((uint2*)g_xl)[i] = make_uint2(lo[0], lo[1]);
    }
    for (int i = gtid; i < NG * NI / 4; i += nthr) {
        float4 v = __ldg((const float4*)Wih + i);
        const float* f = (const float*)&v;
        unsigned hi[2] = {0, 0}, lo[2] = {0, 0};
#pragma unroll
        for (int j = 0; j < 4; j++) {
            __nv_bfloat16 h = __float2bfloat16_rn(f[j]);
            __nv_bfloat16 l = __float2bfloat16_rn(f[j] - __bfloat162float(h));
            hi[j >> 1] |= (unsigned)__bfloat16_as_ushort(h) << ((j & 1) * 16);
            lo[j >> 1] |= (unsigned)__bfloat16_as_ushort(l) << ((j & 1) * 16);
        }
        ((uint2*)g_wh)[i] = make_uint2(hi[0], hi[1]);
        ((uint2*)g_wl)[i] = make_uint2(lo[0], lo[1]);
    }
}

// ---------------- mma.sync GEMM (unchanged — passing) ----------------
#define GHDR 1024
#define PANEL 16384
#define GBUF (4 * PANEL)

__device__ __forceinline__ void gemm_load_stage(uint32_t sb, uint32_t bufb, int kb,
                                                int tid, int m0, int n0) {
#pragma unroll
    for (int i = 0; i < 16; i++) {
        const int idx = tid + i * 256;
        const int panel = idx >> 10;
        const int row = (idx >> 3) & 127;
        const int sg = idx & 7;
        const __nv_bfloat16* src;
        if (panel == 0)      src = g_xh + (size_t)(m0 + row) * NI + kb + 8 * sg;
        else if (panel == 1) src = g_xl + (size_t)(m0 + row) * NI + kb + 8 * sg;
        else if (panel == 2) src = g_wh + (size_t)(n0 + row) * NI + kb + 8 * sg;
        else                 src = g_wl + (size_t)(n0 + row) * NI + kb + 8 * sg;
        CP_ASYNC16(sb + bufb + panel * PANEL + swz(row * 128 + sg * 16), src);
    }
}

__global__ void __launch_bounds__(256) k_gemm_mma(const float* __restrict__ bih,
                                                  const float* __restrict__ bhh) {
    extern __shared__ char smem[];
    const uint32_t sb = smem_u32(smem);
    const int tid = threadIdx.x;
    const int wid = tid >> 5;
    const int lane = tid & 31;
    const int n0 = blockIdx.x * 128;
    const int m0 = blockIdx.y * 128;
    float* sBias = (float*)smem;

    const int wm = wid & 1;
    const int wn = wid >> 1;

    if (tid < 128) sBias[tid] = __ldg(bih + n0 + tid) + __ldg(bhh + n0 + tid);

    uint32_t baseA[4], xorA[4];
#pragma unroll
    for (int mt = 0; mt < 4; mt++) {
        const int rA = wm * 64 + mt * 16 + (lane & 15);
        baseA[mt] = (uint32_t)rA * 128;
        xorA[mt] = (uint32_t)(rA & 7) << 4;
    }
    const uint32_t cA0 = (uint32_t)(lane >> 4) * 16;
    const int gB = lane >> 3;
    uint32_t baseB[2], xorB[2];
#pragma unroll
    for (int pr = 0; pr < 2; pr++) {
        const int rB = wn * 32 + pr * 16 + ((gB >> 1) << 3) + (lane & 7);
        baseB[pr] = (uint32_t)rB * 128;
        xorB[pr] = (uint32_t)(rB & 7) << 4;
    }
    const uint32_t cB0 = (uint32_t)(gB & 1) * 16;

    float acc[4][4][4];
#pragma unroll
    for (int mt = 0; mt < 4; mt++)
#pragma unroll
        for (int nt = 0; nt < 4; nt++)
#pragma unroll
            for (int e = 0; e < 4; e++) acc[mt][nt][e] = 0.0f;

    gemm_load_stage(sb, GHDR, 0, tid, m0, n0);
    CP_COMMIT();

    for (int s = 0; s < 8; s++) {
        const uint32_t bufb = GHDR + (uint32_t)(s & 1) * GBUF;
        if (s < 7) {
            gemm_load_stage(sb, GHDR + (uint32_t)((s + 1) & 1) * GBUF, (s + 1) * 64, tid, m0, n0);
            CP_COMMIT();
            asm volatile("cp.async.wait_group 1;" ::: "memory");
        } else {
            asm volatile("cp.async.wait_group 0;" ::: "memory");
        }
        __syncthreads();

        const uint32_t pAh = sb + bufb + 0 * PANEL;
        const uint32_t pAl = sb + bufb + 1 * PANEL;
        const uint32_t pBh = sb + bufb + 2 * PANEL;
        const uint32_t pBl = sb + bufb + 3 * PANEL;

#pragma unroll
        for (int k16 = 0; k16 < 4; k16++) {
            const uint32_t cA = (uint32_t)k16 * 32 + cA0;
            const uint32_t cB = (uint32_t)k16 * 32 + cB0;

            uint32_t ah[4][4], al[4][4], bh[2][4], bl[2][4];
#pragma unroll
            for (int mt = 0; mt < 4; mt++) {
                LDSM_X4(ah[mt][0], ah[mt][1], ah[mt][2], ah[mt][3],
                        pAh + baseA[mt] + (cA ^ xorA[mt]));
                LDSM_X4(al[mt][0], al[mt][1], al[mt][2], al[mt][3],
                        pAl + baseA[mt] + (cA ^ xorA[mt]));
            }
#pragma unroll
            for (int pr = 0; pr < 2; pr++) {
                LDSM_X4(bh[pr][0], bh[pr][1], bh[pr][2], bh[pr][3],
                        pBh + baseB[pr] + (cB ^ xorB[pr]));
                LDSM_X4(bl[pr][0], bl[pr][1], bl[pr][2], bl[pr][3],
                        pBl + baseB[pr] + (cB ^ xorB[pr]));
            }
#pragma unroll
            for (int mt = 0; mt < 4; mt++)
#pragma unroll
                for (int nt = 0; nt < 4; nt++) {
                    const int pr = nt >> 1;
                    const int sub = nt & 1;
                    MMA16816(acc[mt][nt], ah[mt], bh[pr][sub * 2], bh[pr][sub * 2 + 1]);
                    MMA16816(acc[mt][nt], al[mt], bh[pr][sub * 2], bh[pr][sub * 2 + 1]);
                    MMA16816(acc[mt][nt], ah[mt], bl[pr][sub * 2], bl[pr][sub * 2 + 1]);
                }
        }
        __syncthreads();
    }

    const int b = m0 >> 10;
#pragma unroll
    for (int mt = 0; mt < 4; mt++) {
        const int mrow0 = m0 + wm * 64 + mt * 16 + (lane >> 2);
        const int t0 = mrow0 & (NT - 1);
        const int t1 = (mrow0 + 8) & (NT - 1);
        float* d0 = g_xg + ((size_t)t0 * NB + b) * NG + n0;
        float* d1 = g_xg + ((size_t)t1 * NB + b) * NG + n0;
#pragma unroll
        for (int nt = 0; nt < 4; nt++) {
            const int bn = wn * 32 + nt * 8 + 2 * (lane & 3);
            const float bz0 = sBias[bn], bz1 = sBias[bn + 1];
            *(float2*)(d0 + bn) = make_float2(acc[mt][nt][0] + bz0, acc[mt][nt][1] + bz1);
            *(float2*)(d1 + bn) = make_float2(acc[mt][nt][2] + bz0, acc[mt][nt][3] + bz1);
        }
    }
}

// ---------------- persistent tensor-core scan (v8) ----------------
// v8 = v6 (R14, 3131us) + shuffle-fused gate/cell phase + deferred out store.
// Barrier: R14 atomic counter (red.release + single-word acquire poll by tid0).
// Gate roles: thread (warp w, lane l) owns gate q = l>>3 of pair p = w*8+(l&7)
// (pair = unit*8 + batch, unit = w, batch = l&7). sRed columns scrambled as
// q*128 + ((p + 8q) & 127) so both the partial store and the gate reduce are
// bank-conflict-free. The 4 gates of a pair sit in one warp -> 3 shfl gather,
// cell update in lanes 0-7. No sFin, one less __syncthreads.
#define HROW 1040
#define SOFF_HI 0
#define SOFF_LO (GBATCH * HROW)              // 8320
#define SOFF_RED (2 * GBATCH * HROW)         // 16640
#define SCAN_SMEM (SOFF_RED + 8 * 512 * 4)   // 33024

__global__ void __launch_bounds__(SCAN_THREADS, 1) k_scan(float* __restrict__ out,
                                                          const float* __restrict__ Whh) {
    extern __shared__ char sm[];
    const uint32_t sb = smem_u32(sm);
    float* sRed = (float*)(sm + SOFF_RED);

    const int tid = threadIdx.x;
    const int bid = blockIdx.x;
    const int gid = bid >> 5;
    const int j0 = (bid & 31) * 16;
    const int wid = tid >> 5;
    const int lane = tid & 31;
    const int kc = wid >> 1;          // k in [64kc, 64kc+64)
    const int mh = wid & 1;           // rows mh*32 .. +31

    // ---- build W_hh fragments directly from global fp32 (A-frag lane map) ----
    uint32_t ah[2][4][4], al[2][4][4];
#pragma unroll
    for (int mt = 0; mt < 2; mt++) {
        const int mlo = mh * 32 + mt * 16 + (lane >> 2);
        const int mhi2 = mlo + 8;
        const size_t row0 = (size_t)((mlo >> 4) * 512 + j0 + (mlo & 15)) * NH;
        const size_t row1 = (size_t)((mhi2 >> 4) * 512 + j0 + (mhi2 & 15)) * NH;
#pragma unroll
        for (int ks = 0; ks < 4; ks++) {
            const int kb = kc * 64 + ks * 16 + 2 * (lane & 3);
            float2 v00 = *(const float2*)(Whh + row0 + kb);
            float2 v10 = *(const float2*)(Whh + row1 + kb);
            float2 v01 = *(const float2*)(Whh + row0 + kb + 8);
            float2 v11 = *(const float2*)(Whh + row1 + kb + 8);
            ah[mt][ks][0] = pack_hilo2(v00.x, v00.y, al[mt][ks][0]);
            ah[mt][ks][1] = pack_hilo2(v10.x, v10.y, al[mt][ks][1]);
            ah[mt][ks][2] = pack_hilo2(v01.x, v01.y, al[mt][ks][2]);
            ah[mt][ks][3] = pack_hilo2(v11.x, v11.y, al[mt][ks][3]);
        }
    }

    // B ldmatrix per-lane base: row = lane&7 (batch), k-byte = (lane>>3)*16
    const uint32_t bOff = (uint32_t)(lane & 7) * HROW + (uint32_t)(lane >> 3) * 16;

    // gate/cell roles: q = lane>>3, pair p = wid*8 + (lane&7)
    const int gq = lane >> 3;
    const int gfb = lane & 7;              // batch within group
    const int gfu = wid;                   // unit within block
    const int gp = wid * 8 + gfb;          // pair index 0..127
    const int colG = gq * 128 + ((gp + 8 * gq) & 127);
    const int ggb = gid * GBATCH + gfb;    // global batch
    const int jpub = j0 + gfu;             // unit j for publish (lanes<8)

    float creg = 0.0f;                     // valid in lanes 0-7
    float pend = 0.0f;                     // deferred out value (lanes 0-7)

    // per-thread xg prefetch (one value: gate gq of unit gfu, batch ggb)
    float xgv = __ldcg(g_xg + ((size_t)ggb) * NG + gq * 512 + jpub);

    const int m0r = lane >> 2;
    const int bc0 = 2 * (lane & 3);

    unsigned bar_tgt = 0;
    unsigned* const barp = &g_bars[gid * 32];

    for (int t = 0; t < NT; t++) {
        const int cur = t & 1;
        const int nxt = cur ^ 1;

        // ---- stage group's h hi/lo (8KB each) ----
        {
            const uint4* srcH = (const uint4*)&g_hh[cur][gid * GBATCH * NH];
            const uint4* srcL = (const uint4*)&g_hl[cur][gid * GBATCH * NH];
            const int b = tid >> 6;
            const int kch = tid & 63;
            uint4 vh = __ldcg(srcH + tid);
            uint4 vl = __ldcg(srcL + tid);
            *(uint4*)(sm + SOFF_HI + b * HROW + kch * 16) = vh;
            *(uint4*)(sm + SOFF_LO + b * HROW + kch * 16) = vl;
        }
        __syncthreads();

        // ---- tensor dot: 4 LDSM.x4 + 24 mma ----
        float acc[2][4];
#pragma unroll
        for (int mt = 0; mt < 2; mt++)
#pragma unroll
            for (int e = 0; e < 4; e++) acc[mt][e] = 0.0f;

#pragma unroll
        for (int kh = 0; kh < 2; kh++) {
            const uint32_t cofs = (uint32_t)(kc * 64 + kh * 32) * 2;
            uint32_t bh[4], bl[4];
            LDSM_X4(bh[0], bh[1], bh[2], bh[3], sb + SOFF_HI + bOff + cofs);
            LDSM_X4(bl[0], bl[1], bl[2], bl[3], sb + SOFF_LO + bOff + cofs);
#pragma unroll
            for (int ki = 0; ki < 2; ki++) {
                const int ks = kh * 2 + ki;
#pragma unroll
                for (int mt = 0; mt < 2; mt++) {
                    MMA16816(acc[mt], ah[mt][ks], bh[ki * 2], bh[ki * 2 + 1]);
                    MMA16816(acc[mt], al[mt][ks], bh[ki * 2], bh[ki * 2 + 1]);
                    MMA16816(acc[mt], ah[mt][ks], bl[ki * 2], bl[ki * 2 + 1]);
                }
            }
        }

        // ---- store partials at scrambled cols: q*128 + ((u*8+b + 8q)&127) ----
#pragma unroll
        for (int mt = 0; mt < 2; mt++) {
            const int mA = mh * 32 + mt * 16 + m0r;
            const int q = mA >> 4;
            const int u8b = (mA & 15) * 8 + bc0;
            const int cA = q * 128 + ((u8b + 8 * q) & 127);
            const int cB = q * 128 + ((u8b + 64 + 8 * q) & 127);
            *(float2*)&sRed[kc * 512 + cA] = make_float2(acc[mt][0], acc[mt][1]);
            *(float2*)&sRed[kc * 512 + cB] = make_float2(acc[mt][2], acc[mt][3]);
        }
        __syncthreads();

        // ---- fused gate + cell phase (no extra sync; shfl gather) ----
        {
            float s = xgv;
#pragma unroll
            for (int r = 0; r < 8; r++) s += sRed[r * 512 + colG];
            if (t + 1 < NT)
                xgv = __ldcg(g_xg + ((size_t)(t + 1) * NB + ggb) * NG + gq * 512 + jpub);
            const float act = (gq == 2) ? tanhfast(s) : sigf(s);

            const unsigned FULL = 0xffffffffu;
            const int bl8 = lane & 7;
            const float a1 = __shfl_sync(FULL, act, bl8 + 8);    // fg
            const float a2 = __shfl_sync(FULL, act, bl8 + 16);   // gv
            const float a3 = __shfl_sync(FULL, act, bl8 + 24);   // og

            if (lane < 8) {
                creg = a1 * creg + act * a2;           // fg*c + ig*gv
                const float hn = a3 * tanhfast(creg);  // og * tanh(c)
                pend = hn;

                const int b = gid * GBATCH + lane;
                const __nv_bfloat16 hh = __float2bfloat16_rn(hn);
                const __nv_bfloat16 hl = __float2bfloat16_rn(hn - __bfloat162float(hh));
                g_hh[nxt][b * NH + jpub] = __bfloat16_as_ushort(hh);
                g_hl[nxt][b * NH + jpub] = __bfloat16_as_ushort(hl);

                if (t == NT - 1) {
                    out[(size_t)NB * NT * NH + (size_t)b * NH + jpub] = hn;
                    out[(size_t)NB * NT * NH + (size_t)NB * NH + (size_t)b * NH + jpub] = creg;
                }
            }
        }
        __syncthreads();

        // ---- group barrier (R14 proven: counter + single-word acquire poll) ----
        if (tid == 0) {
            asm volatile("red.release.gpu.add.u32 [%0], %1;" :: "l"(barp), "r"(1u) : "memory");
            bar_tgt += GBLK;
            unsigned v;
            do {
                asm volatile("ld.acquire.gpu.u32 %0, [%1];" : "=r"(v) : "l"(barp) : "memory");
            } while (v < bar_tgt);
        }
        __syncthreads();

        // ---- deferred out store (off the release-critical path) ----
        if (lane < 8)
            out[((size_t)(gid * GBATCH + lane) * NT + t) * NH + jpub] = pend;
    }
}

// ---------------- launch ----------------
extern "C" void kernel_launch(void* const* d_in, const int* in_sizes, int n_in,
                              void* d_out, int out_size) {
    const float* x    = (const float*)d_in[0];
    const float* Wih  = (const float*)d_in[1];
    const float* Whh  = (const float*)d_in[2];
    const float* bih  = (const float*)d_in[3];
    const float* bhh  = (const float*)d_in[4];
    float* out = (float*)d_out;

    const int gemm_smem = GHDR + 2 * GBUF;   // 132,096 B
    cudaFuncSetAttribute(k_gemm_mma, cudaFuncAttributeMaxDynamicSharedMemorySize, gemm_smem);
    cudaFuncSetAttribute(k_scan, cudaFuncAttributeMaxDynamicSharedMemorySize, SCAN_SMEM);

    k_split<<<1024, 256>>>(x, Wih);

    dim3 ggrid(NG / 128, (NB * NT) / 128);   // (16, 256)
    k_gemm_mma<<<ggrid, 256, gemm_smem>>>(bih, bhh);

    k_scan<<<SCAN_BLOCKS, SCAN_THREADS, SCAN_SMEM>>>(out, Whh);
}